// round 1
// baseline (speedup 1.0000x reference)
#include <cuda_runtime.h>
#include <cstdint>

// FP4Quantizer: per-64-block adaptive (95th-percentile) scale, FP4-table
// quant-dequant with double-quantized scales (global min/max over scales).
//
// Pipeline (4 graph nodes):
//   init_kernel   : reset global min/max accumulators
//   pass1_kernel  : per-block scale via top-5 |x| selection (warp REDUX),
//                   atomic global min/max of scale bits
//   scale_kernel  : per-block (1/s, deq_s) from global min/max
//   pass2_kernel  : elementwise quantize-dequantize (branchless bit-trick)

#define QBLK 64
#define MAX_QBLOCKS (262144 + 4096)

__device__ float    g_scales[MAX_QBLOCKS];
__device__ float2   g_bs[MAX_QBLOCKS];     // (inv_scale, deq_scale)
__device__ unsigned g_min_bits;
__device__ unsigned g_max_bits;

__global__ void init_kernel() {
    g_min_bits = 0xFFFFFFFFu;
    g_max_bits = 0u;
}

// Pass 1: one warp per quant-block. Each lane holds |x| bit patterns of 2
// elements; 5 rounds of warp-max extraction (REDUX on u32 — positive float
// bits are order-preserving) yield the 4th and 5th largest.
__global__ void pass1_kernel(const float* __restrict__ x, int n, int nblocks) {
    const int lane    = threadIdx.x & 31;
    const int warp_g  = (blockIdx.x * blockDim.x + threadIdx.x) >> 5;
    const int nwarps  = (gridDim.x * blockDim.x) >> 5;

    unsigned my_min = 0xFFFFFFFFu;
    unsigned my_max = 0u;

    for (int b = warp_g; b < nblocks; b += nwarps) {
        long base = (long)b * QBLK + lane * 2;
        float x0 = 0.0f, x1 = 0.0f;
        if (base + 1 < (long)n) {
            float2 v = *reinterpret_cast<const float2*>(x + base);
            x0 = v.x; x1 = v.y;
        } else if (base < (long)n) {
            x0 = x[base];
        }
        unsigned a0 = __float_as_uint(x0) & 0x7FFFFFFFu;
        unsigned a1 = __float_as_uint(x1) & 0x7FFFFFFFu;

        unsigned w4 = 0u, w5 = 0u;
        #pragma unroll
        for (int r = 0; r < 5; ++r) {
            unsigned m = a0 > a1 ? a0 : a1;
            unsigned w = __reduce_max_sync(0xFFFFFFFFu, m);
            if (r == 3) w4 = w;           // 4th largest  -> sorted[60]
            if (r == 4) { w5 = w; }       // 5th largest  -> sorted[59]
            else {
                unsigned bal = __ballot_sync(0xFFFFFFFFu, m == w);
                if (lane == (__ffs((int)bal) - 1)) {
                    if (a0 == w) a0 = 0u; else a1 = 0u;
                }
            }
        }

        if (lane == 0) {
            float q4 = __uint_as_float(w4);
            float q5 = __uint_as_float(w5);
            // jnp.quantile linear: idx = 0.95*(64-1) = 59.85
            float s = q5 + 0.85f * (q4 - q5);
            s = fmaxf(s, 1e-8f);
            g_scales[b] = s;
            unsigned sb = __float_as_uint(s);
            my_min = my_min < sb ? my_min : sb;
            my_max = my_max > sb ? my_max : sb;
        }
    }
    if (lane == 0) {
        atomicMin(&g_min_bits, my_min);   // harmless if warp did no work
        atomicMax(&g_max_bits, my_max);
    }
}

// Pass 1.5: per-block reciprocal + dequantized scale (double quantization;
// NOTE: faithful to reference — deq drops smin).
__global__ void scale_kernel(int nblocks) {
    int i = blockIdx.x * blockDim.x + threadIdx.x;
    if (i >= nblocks) return;
    float smin = __uint_as_float(g_min_bits);
    float smax = __uint_as_float(g_max_bits);
    float s = g_scales[i];
    float deq;
    if (smax > smin) {
        float ss = (smax - smin) / 255.0f;
        float q  = fminf(fmaxf(rintf((s - smin) / ss), 0.0f), 255.0f);
        deq = q * ss;
    } else {
        deq = 0.0f;   // q_scales = 0, scale_scale = 1
    }
    g_bs[i] = make_float2(1.0f / s, deq);
}

// Branchless nearest-level for table {0, ±0.75, ±1, ±1.5, ±2, ±3}:
// round |x/s| to 1 mantissa bit (half-ulp add + mask), clamp to [0.75, 3.0]
// as u32 (valid for positive floats), zero below/at 0.375 (strict >, matching
// argmin tie-to-lower-index), then scale by deq and restore sign.
__device__ __forceinline__ float qdq_one(float xv, float inv, float deq) {
    float xs = xv * inv;
    unsigned ub = __float_as_uint(xs);
    unsigned u  = ub & 0x7FFFFFFFu;
    unsigned t  = (u + 0x00200000u) & 0xFFC00000u;
    t = t < 0x40400000u ? t : 0x40400000u;   // min(t, 3.0)
    t = t > 0x3F400000u ? t : 0x3F400000u;   // max(t, 0.75)
    float lvl = (u > 0x3EC00000u) ? __uint_as_float(t) : 0.0f;  // > 0.375
    float o = lvl * deq;
    return __uint_as_float(__float_as_uint(o) | (ub & 0x80000000u));
}

__global__ void pass2_kernel(const float* __restrict__ x,
                             float* __restrict__ out, int n) {
    const int tid = blockIdx.x * blockDim.x + threadIdx.x;
    const int nthreads = gridDim.x * blockDim.x;
    const int nquads = n >> 2;          // full float4s

    const float4* __restrict__ x4 = reinterpret_cast<const float4*>(x);
    float4* __restrict__ o4 = reinterpret_cast<float4*>(out);

    for (int q = tid; q < nquads; q += nthreads) {
        int b = q >> 4;                 // 16 quads per 64-elem block
        float2 bs = g_bs[b];
        float4 v = x4[q];
        float4 r;
        r.x = qdq_one(v.x, bs.x, bs.y);
        r.y = qdq_one(v.y, bs.x, bs.y);
        r.z = qdq_one(v.z, bs.x, bs.y);
        r.w = qdq_one(v.w, bs.x, bs.y);
        o4[q] = r;
    }
    // scalar tail (n not multiple of 4)
    int tail_start = nquads << 2;
    for (int i = tail_start + tid; i < n; i += nthreads) {
        int b = i >> 6;
        float2 bs = g_bs[b];
        out[i] = qdq_one(x[i], bs.x, bs.y);
    }
}

extern "C" void kernel_launch(void* const* d_in, const int* in_sizes, int n_in,
                              void* d_out, int out_size) {
    const float* x = (const float*)d_in[0];
    float* out = (float*)d_out;
    int n = in_sizes[0];
    int nblocks = (n + QBLK - 1) / QBLK;

    init_kernel<<<1, 1>>>();
    pass1_kernel<<<4096, 256>>>(x, n, nblocks);
    scale_kernel<<<(nblocks + 255) / 256, 256>>>(nblocks);
    pass2_kernel<<<4096, 256>>>(x, out, n);
}

// round 2
// speedup vs baseline: 1.1878x; 1.1878x over previous
#include <cuda_runtime.h>
#include <cstdint>

// FP4Quantizer: per-64-block adaptive (95th-percentile) scale, FP4-table
// quant-dequant with double-quantized scales (global min/max over scales).
//
// 3 graph nodes:
//   init_kernel  : reset global scale-min/max accumulators
//   pass1_*      : per-block scale via top-5 |x| selection (warp REDUX),
//                  ILP-2 over block pairs, CTA-reduced global min/max
//   pass2_kernel : elementwise quantize-dequantize, deq(s) inline,
//                  4-way batched loads + streaming stores

#define QBLK 64
#define MAX_QBLOCKS (262144 + 4096)

__device__ float2   g_bs[MAX_QBLOCKS];   // (inv_scale, scale)
__device__ unsigned g_min_bits;
__device__ unsigned g_max_bits;

__global__ void init_kernel() {
    g_min_bits = 0xFFFFFFFFu;
    g_max_bits = 0u;
}

__device__ __forceinline__ unsigned absbits(float f) {
    return __float_as_uint(f) & 0x7FFFFFFFu;
}

// ---------------- Pass 1 (fast path: n % 128 == 0) ----------------
// One warp processes TWO 64-elem blocks per iteration; the two 5-round
// max-extract chains are interleaved for ILP. Positive-float bit patterns
// are order-preserving as u32, so REDUX.MAX on bits == max on |x|.
// Each round removes exactly one instance of the current max (ties handled:
// one copy removed per round), so round 3 / round 4 yield the 4th / 5th
// largest == sorted[60] / sorted[59]; quantile(0.95) = s59 + 0.85*(s60-s59).
__global__ void pass1_pair(const float* __restrict__ x, int npairs) {
    const int lane = threadIdx.x & 31;
    const int warp = (blockIdx.x * blockDim.x + threadIdx.x) >> 5;
    const int nw   = (gridDim.x * blockDim.x) >> 5;
    unsigned mymin = 0xFFFFFFFFu, mymax = 0u;

    for (int p = warp; p < npairs; p += nw) {
        long base = (long)p * (2 * QBLK) + lane * 2;
        float2 u = *reinterpret_cast<const float2*>(x + base);
        float2 v = *reinterpret_cast<const float2*>(x + base + QBLK);
        unsigned a0 = absbits(u.x), a1 = absbits(u.y);
        unsigned c0 = absbits(v.x), c1 = absbits(v.y);
        unsigned w4a = 0u, w5a = 0u, w4b = 0u, w5b = 0u;
        #pragma unroll
        for (int r = 0; r < 5; ++r) {
            unsigned ma = a0 > a1 ? a0 : a1;
            unsigned mb = c0 > c1 ? c0 : c1;
            unsigned wa = __reduce_max_sync(0xFFFFFFFFu, ma);
            unsigned wb = __reduce_max_sync(0xFFFFFFFFu, mb);
            if (r == 3) { w4a = wa; w4b = wb; }
            if (r == 4) { w5a = wa; w5b = wb; }
            else {
                unsigned bala = __ballot_sync(0xFFFFFFFFu, ma == wa);
                unsigned balb = __ballot_sync(0xFFFFFFFFu, mb == wb);
                if (lane == __ffs((int)bala) - 1) { if (a0 == wa) a0 = 0u; else a1 = 0u; }
                if (lane == __ffs((int)balb) - 1) { if (c0 == wb) c0 = 0u; else c1 = 0u; }
            }
        }
        float sA = fmaxf(fmaf(0.85f, __uint_as_float(w4a) - __uint_as_float(w5a),
                              __uint_as_float(w5a)), 1e-8f);
        float sB = fmaxf(fmaf(0.85f, __uint_as_float(w4b) - __uint_as_float(w5b),
                              __uint_as_float(w5b)), 1e-8f);
        if (lane == 0) {
            g_bs[2 * p]     = make_float2(1.0f / sA, sA);
            g_bs[2 * p + 1] = make_float2(1.0f / sB, sB);
            unsigned sa = __float_as_uint(sA), sb = __float_as_uint(sB);
            unsigned lo = sa < sb ? sa : sb;
            unsigned hi = sa > sb ? sa : sb;
            mymin = mymin < lo ? mymin : lo;
            mymax = mymax > hi ? mymax : hi;
        }
    }

    // CTA-level reduction before global atomics (avoid 64K same-address atoms)
    __shared__ unsigned s_min[8], s_max[8];
    int wci = threadIdx.x >> 5;
    if (lane == 0) { s_min[wci] = mymin; s_max[wci] = mymax; }
    __syncthreads();
    if (threadIdx.x == 0) {
        unsigned m0 = 0xFFFFFFFFu, m1 = 0u;
        int nwc = blockDim.x >> 5;
        for (int i = 0; i < nwc; ++i) {
            m0 = m0 < s_min[i] ? m0 : s_min[i];
            m1 = m1 > s_max[i] ? m1 : s_max[i];
        }
        atomicMin(&g_min_bits, m0);
        atomicMax(&g_max_bits, m1);
    }
}

// ---------------- Pass 1 (generic fallback, any n) ----------------
__global__ void pass1_generic(const float* __restrict__ x, int n, int nblocks) {
    const int lane = threadIdx.x & 31;
    const int warp = (blockIdx.x * blockDim.x + threadIdx.x) >> 5;
    const int nw   = (gridDim.x * blockDim.x) >> 5;
    unsigned mymin = 0xFFFFFFFFu, mymax = 0u;

    for (int b = warp; b < nblocks; b += nw) {
        long base = (long)b * QBLK + lane * 2;
        float x0 = 0.0f, x1 = 0.0f;
        if (base + 1 < (long)n) {
            float2 t = *reinterpret_cast<const float2*>(x + base);
            x0 = t.x; x1 = t.y;
        } else if (base < (long)n) {
            x0 = x[base];
        }
        unsigned a0 = absbits(x0), a1 = absbits(x1);
        unsigned w4 = 0u, w5 = 0u;
        #pragma unroll
        for (int r = 0; r < 5; ++r) {
            unsigned m = a0 > a1 ? a0 : a1;
            unsigned w = __reduce_max_sync(0xFFFFFFFFu, m);
            if (r == 3) w4 = w;
            if (r == 4) w5 = w;
            else {
                unsigned bal = __ballot_sync(0xFFFFFFFFu, m == w);
                if (lane == __ffs((int)bal) - 1) { if (a0 == w) a0 = 0u; else a1 = 0u; }
            }
        }
        float s = fmaxf(fmaf(0.85f, __uint_as_float(w4) - __uint_as_float(w5),
                             __uint_as_float(w5)), 1e-8f);
        if (lane == 0) {
            g_bs[b] = make_float2(1.0f / s, s);
            unsigned sb = __float_as_uint(s);
            mymin = mymin < sb ? mymin : sb;
            mymax = mymax > sb ? mymax : sb;
        }
    }
    __shared__ unsigned s_min[8], s_max[8];
    int wci = threadIdx.x >> 5;
    if (lane == 0) { s_min[wci] = mymin; s_max[wci] = mymax; }
    __syncthreads();
    if (threadIdx.x == 0) {
        unsigned m0 = 0xFFFFFFFFu, m1 = 0u;
        int nwc = blockDim.x >> 5;
        for (int i = 0; i < nwc; ++i) {
            m0 = m0 < s_min[i] ? m0 : s_min[i];
            m1 = m1 > s_max[i] ? m1 : s_max[i];
        }
        atomicMin(&g_min_bits, m0);
        atomicMax(&g_max_bits, m1);
    }
}

// ---------------- Pass 2 ----------------
// Branchless nearest-level for {0, ±0.75, ±1, ±1.5, ±2, ±3}: round |x/s| to
// 1 mantissa bit (half-ulp add + mask), clamp [0.75, 3.0] as u32, zero at or
// below 0.375, multiply by deq, restore sign.
__device__ __forceinline__ float qdq_one(float xv, float inv, float deq) {
    float xs = xv * inv;
    unsigned ub = __float_as_uint(xs);
    unsigned uu = ub & 0x7FFFFFFFu;
    unsigned t  = (uu + 0x00200000u) & 0xFFC00000u;
    t = t < 0x40400000u ? t : 0x40400000u;   // min(t, 3.0)
    t = t > 0x3F400000u ? t : 0x3F400000u;   // max(t, 0.75)
    float lvl = (uu > 0x3EC00000u) ? __uint_as_float(t) : 0.0f;  // > 0.375
    float o = lvl * deq;
    return __uint_as_float(__float_as_uint(o) | (ub & 0x80000000u));
}

// deq(s): double-quantized scale. rss==0 when smax<=smin gives q=0, deq=0,
// matching the reference's degenerate branch.
__device__ __forceinline__ float deq_of(float s, float smin, float rss, float ss) {
    float q = rintf((s - smin) * rss);
    q = fminf(fmaxf(q, 0.0f), 255.0f);
    return q * ss;
}

__global__ void pass2_kernel(const float* __restrict__ x,
                             float* __restrict__ out, int n) {
    const int tid = blockIdx.x * blockDim.x + threadIdx.x;
    const int NT  = gridDim.x * blockDim.x;
    const int nquads = n >> 2;

    float smin = __uint_as_float(g_min_bits);
    float smax = __uint_as_float(g_max_bits);
    bool  cond = smax > smin;
    float d    = smax - smin;
    float ss   = cond ? d * (1.0f / 255.0f) : 1.0f;
    float rss  = cond ? 255.0f / d : 0.0f;

    const float4* __restrict__ x4 = reinterpret_cast<const float4*>(x);
    float4* __restrict__ o4 = reinterpret_cast<float4*>(out);

    int q = tid;
    for (; q + 3 * NT < nquads; q += 4 * NT) {
        int q1 = q + NT, q2 = q + 2 * NT, q3 = q + 3 * NT;
        float2 b0 = g_bs[q  >> 4];
        float2 b1 = g_bs[q1 >> 4];
        float2 b2 = g_bs[q2 >> 4];
        float2 b3 = g_bs[q3 >> 4];
        float4 v0 = x4[q],  v1 = x4[q1], v2 = x4[q2], v3 = x4[q3];
        float d0 = deq_of(b0.y, smin, rss, ss);
        float d1 = deq_of(b1.y, smin, rss, ss);
        float d2 = deq_of(b2.y, smin, rss, ss);
        float d3 = deq_of(b3.y, smin, rss, ss);
        float4 r0, r1, r2, r3;
        r0.x = qdq_one(v0.x, b0.x, d0); r0.y = qdq_one(v0.y, b0.x, d0);
        r0.z = qdq_one(v0.z, b0.x, d0); r0.w = qdq_one(v0.w, b0.x, d0);
        r1.x = qdq_one(v1.x, b1.x, d1); r1.y = qdq_one(v1.y, b1.x, d1);
        r1.z = qdq_one(v1.z, b1.x, d1); r1.w = qdq_one(v1.w, b1.x, d1);
        r2.x = qdq_one(v2.x, b2.x, d2); r2.y = qdq_one(v2.y, b2.x, d2);
        r2.z = qdq_one(v2.z, b2.x, d2); r2.w = qdq_one(v2.w, b2.x, d2);
        r3.x = qdq_one(v3.x, b3.x, d3); r3.y = qdq_one(v3.y, b3.x, d3);
        r3.z = qdq_one(v3.z, b3.x, d3); r3.w = qdq_one(v3.w, b3.x, d3);
        __stcs(o4 + q,  r0);
        __stcs(o4 + q1, r1);
        __stcs(o4 + q2, r2);
        __stcs(o4 + q3, r3);
    }
    for (; q < nquads; q += NT) {
        float2 b = g_bs[q >> 4];
        float dq = deq_of(b.y, smin, rss, ss);
        float4 v = x4[q];
        float4 r;
        r.x = qdq_one(v.x, b.x, dq); r.y = qdq_one(v.y, b.x, dq);
        r.z = qdq_one(v.z, b.x, dq); r.w = qdq_one(v.w, b.x, dq);
        __stcs(o4 + q, r);
    }
    // scalar tail (n not multiple of 4)
    for (int i = (nquads << 2) + tid; i < n; i += NT) {
        float2 b = g_bs[i >> 6];
        float dq = deq_of(b.y, smin, rss, ss);
        out[i] = qdq_one(x[i], b.x, dq);
    }
}

extern "C" void kernel_launch(void* const* d_in, const int* in_sizes, int n_in,
                              void* d_out, int out_size) {
    const float* x = (const float*)d_in[0];
    float* out = (float*)d_out;
    int n = in_sizes[0];
    int nblocks = (n + QBLK - 1) / QBLK;

    init_kernel<<<1, 1>>>();
    if ((n & 127) == 0) {
        pass1_pair<<<4096, 256>>>(x, n >> 7);
    } else {
        pass1_generic<<<4096, 256>>>(x, n, nblocks);
    }
    pass2_kernel<<<4096, 256>>>(x, out, n);
}